// round 2
// baseline (speedup 1.0000x reference)
#include <cuda_runtime.h>
#include <cuda_bf16.h>
#include <math.h>
#include <stdint.h>

#define L 6400
#define CDIM 256
#define HW 80
#define MARG 2
#define TILE 128
#define NT (L / TILE)   // 50

__device__ __nv_bfloat16 g_x0[L * CDIM];
__device__ __nv_bfloat16 g_x1[L * CDIM];
__device__ float g_sim[(size_t)L * L];
__device__ float g_rowPM[NT * L];
__device__ float g_rowPS[NT * L];
__device__ float g_colPM[NT * L];
__device__ float g_colPS[NT * L];
__device__ float g_u[L];
__device__ float g_t[L];
__device__ unsigned long long g_rowBest[L];
__device__ unsigned long long g_colBest[L];

__device__ __forceinline__ void msmerge(float& m, float& s, float om, float os) {
    if (om > m) { s = s * __expf(m - om) + os; m = om; }
    else        { s += os * __expf(om - m); }
}

__device__ __forceinline__ unsigned long long packfi(float v, unsigned idx) {
    unsigned b = __float_as_uint(v);
    b = (b & 0x80000000u) ? ~b : (b | 0x80000000u);
    return ((unsigned long long)b << 32) | (unsigned long long)idx;
}

__device__ __forceinline__ float unpackf(unsigned long long p) {
    unsigned b = (unsigned)(p >> 32);
    b = (b & 0x80000000u) ? (b ^ 0x80000000u) : ~b;
    return __uint_as_float(b);
}

// ---------------------------------------------------------------- convert
__global__ void k_convert(const float* __restrict__ x0, const float* __restrict__ x1) {
    int i = blockIdx.x * blockDim.x + threadIdx.x;
    if (i < L * CDIM) {
        g_x0[i] = __float2bfloat16(x0[i]);
        g_x1[i] = __float2bfloat16(x1[i]);
    }
}

__global__ void k_init() {
    int i = blockIdx.x * blockDim.x + threadIdx.x;
    if (i < L) { g_rowBest[i] = 0ull; g_colBest[i] = 0ull; }
}

__global__ void k_zero(float4* __restrict__ out) {
    size_t n4 = (size_t)L * L / 4;
    for (size_t i = (size_t)blockIdx.x * blockDim.x + threadIdx.x; i < n4;
         i += (size_t)gridDim.x * blockDim.x)
        out[i] = make_float4(0.f, 0.f, 0.f, 0.f);
}

// ---------------------------------------------------------------- GEMM: sim = x0 * x1^T / 25.6
// 128x128 tile per block, 8 warps in 4x2; each warp: 32 rows x 64 cols via m16n8k16 bf16 mma.
__global__ __launch_bounds__(256) void k_gemm() {
    __shared__ __nv_bfloat16 As[TILE][72];
    __shared__ __nv_bfloat16 Bs[TILE][72];
    const int tid = threadIdx.x;
    const int lane = tid & 31, wid = tid >> 5;
    const int wr = wid >> 1, wc = wid & 1;
    const int g = lane >> 2, tg = lane & 3;
    const int brow = blockIdx.y * TILE, bcol = blockIdx.x * TILE;

    float c[2][8][4];
#pragma unroll
    for (int mf = 0; mf < 2; mf++)
#pragma unroll
        for (int nf = 0; nf < 8; nf++)
#pragma unroll
            for (int q = 0; q < 4; q++) c[mf][nf][q] = 0.f;

    for (int kc = 0; kc < CDIM; kc += 64) {
        // load 128x64 bf16 tiles of A and B into smem (stride 72, conflict-free frags)
        for (int x = tid; x < TILE * 8; x += 256) {
            int r = x >> 3, s = x & 7;
            uint4 qa = *(const uint4*)&g_x0[(size_t)(brow + r) * CDIM + kc + s * 8];
            uint4 qb = *(const uint4*)&g_x1[(size_t)(bcol + r) * CDIM + kc + s * 8];
            *(uint2*)&As[r][s * 8]     = make_uint2(qa.x, qa.y);
            *(uint2*)&As[r][s * 8 + 4] = make_uint2(qa.z, qa.w);
            *(uint2*)&Bs[r][s * 8]     = make_uint2(qb.x, qb.y);
            *(uint2*)&Bs[r][s * 8 + 4] = make_uint2(qb.z, qb.w);
        }
        __syncthreads();
#pragma unroll
        for (int kk = 0; kk < 64; kk += 16) {
            unsigned a[2][4], b[8][2];
#pragma unroll
            for (int mf = 0; mf < 2; mf++) {
                int r = wr * 32 + mf * 16;
                a[mf][0] = *(const unsigned*)&As[r + g][kk + 2 * tg];
                a[mf][1] = *(const unsigned*)&As[r + g + 8][kk + 2 * tg];
                a[mf][2] = *(const unsigned*)&As[r + g][kk + 2 * tg + 8];
                a[mf][3] = *(const unsigned*)&As[r + g + 8][kk + 2 * tg + 8];
            }
#pragma unroll
            for (int nf = 0; nf < 8; nf++) {
                int cc = wc * 64 + nf * 8;
                b[nf][0] = *(const unsigned*)&Bs[cc + g][kk + 2 * tg];
                b[nf][1] = *(const unsigned*)&Bs[cc + g][kk + 2 * tg + 8];
            }
#pragma unroll
            for (int mf = 0; mf < 2; mf++)
#pragma unroll
                for (int nf = 0; nf < 8; nf++) {
                    asm volatile(
                        "mma.sync.aligned.m16n8k16.row.col.f32.bf16.bf16.f32 "
                        "{%0,%1,%2,%3},{%4,%5,%6,%7},{%8,%9},{%0,%1,%2,%3};\n"
                        : "+f"(c[mf][nf][0]), "+f"(c[mf][nf][1]),
                          "+f"(c[mf][nf][2]), "+f"(c[mf][nf][3])
                        : "r"(a[mf][0]), "r"(a[mf][1]), "r"(a[mf][2]), "r"(a[mf][3]),
                          "r"(b[nf][0]), "r"(b[nf][1]));
                }
        }
        __syncthreads();
    }

    const float SCALE = 1.0f / 25.6f;
#pragma unroll
    for (int mf = 0; mf < 2; mf++) {
        int r0 = brow + wr * 32 + mf * 16 + g;
#pragma unroll
        for (int nf = 0; nf < 8; nf++) {
            int cb = bcol + wc * 64 + nf * 8 + 2 * tg;
            *(float2*)&g_sim[(size_t)r0 * L + cb] =
                make_float2(c[mf][nf][0] * SCALE, c[mf][nf][1] * SCALE);
            *(float2*)&g_sim[(size_t)(r0 + 8) * L + cb] =
                make_float2(c[mf][nf][2] * SCALE, c[mf][nf][3] * SCALE);
        }
    }
}

// ---------------------------------------------------------------- fused row+col online softmax stats
__global__ __launch_bounds__(256) void k_stats() {
    __shared__ float sCM[8][128];
    __shared__ float sCS[8][128];
    const int tid = threadIdx.x, lane = tid & 31, wid = tid >> 5;
    const int brow = blockIdx.y * TILE, bcol = blockIdx.x * TILE;

    float cm[4], cs[4];
#pragma unroll
    for (int it = 0; it < 4; it++) { cm[it] = -INFINITY; cs[it] = 0.f; }

    for (int r16 = 0; r16 < 16; r16++) {
        int row = brow + wid * 16 + r16;
        const float* p = &g_sim[(size_t)row * L + bcol];
        float rm = -INFINITY, rs = 0.f;
#pragma unroll
        for (int it = 0; it < 4; it++) {
            float v = p[lane + 32 * it];
            if (v > rm) { rs = rs * __expf(rm - v) + 1.f; rm = v; }
            else        { rs += __expf(v - rm); }
            if (v > cm[it]) { cs[it] = cs[it] * __expf(cm[it] - v) + 1.f; cm[it] = v; }
            else            { cs[it] += __expf(v - cm[it]); }
        }
#pragma unroll
        for (int off = 16; off; off >>= 1) {
            float om = __shfl_down_sync(0xffffffffu, rm, off);
            float os = __shfl_down_sync(0xffffffffu, rs, off);
            msmerge(rm, rs, om, os);
        }
        if (lane == 0) {
            g_rowPM[blockIdx.x * L + row] = rm;
            g_rowPS[blockIdx.x * L + row] = rs;
        }
    }
#pragma unroll
    for (int it = 0; it < 4; it++) {
        sCM[wid][lane + 32 * it] = cm[it];
        sCS[wid][lane + 32 * it] = cs[it];
    }
    __syncthreads();
    if (tid < 128) {
        float m = sCM[0][tid], s = sCS[0][tid];
#pragma unroll
        for (int w = 1; w < 8; w++) msmerge(m, s, sCM[w][tid], sCS[w][tid]);
        g_colPM[blockIdx.y * L + bcol + tid] = m;
        g_colPS[blockIdx.y * L + bcol + tid] = s;
    }
}

__global__ void k_combine() {
    int i = blockIdx.x * blockDim.x + threadIdx.x;
    if (i >= L) return;
    float m = -INFINITY, s = 0.f;
    for (int p = 0; p < NT; p++) msmerge(m, s, g_rowPM[p * L + i], g_rowPS[p * L + i]);
    g_u[i] = m + logf(s);
    m = -INFINITY; s = 0.f;
    for (int p = 0; p < NT; p++) msmerge(m, s, g_colPM[p * L + i], g_colPS[p * L + i]);
    g_t[i] = m + logf(s);
}

// ---------------------------------------------------------------- argmax of log-conf along rows and cols
__global__ __launch_bounds__(256) void k_argmax() {
    __shared__ float sT[128];
    __shared__ float sU[128];
    __shared__ float sCm[8][128];
    __shared__ unsigned sCi[8][128];
    const int tid = threadIdx.x, lane = tid & 31, wid = tid >> 5;
    const int brow = blockIdx.y * TILE, bcol = blockIdx.x * TILE;
    if (tid < 128) { sT[tid] = g_t[bcol + tid]; sU[tid] = g_u[brow + tid]; }
    __syncthreads();

    float cbm[4];
    unsigned cbi[4];
#pragma unroll
    for (int it = 0; it < 4; it++) { cbm[it] = -INFINITY; cbi[it] = 0u; }

    for (int r16 = 0; r16 < 16; r16++) {
        int row = brow + wid * 16 + r16;
        float uu = sU[wid * 16 + r16];
        const float* p = &g_sim[(size_t)row * L + bcol];
        float rbm = -INFINITY;
        unsigned rbi = 0u;
#pragma unroll
        for (int it = 0; it < 4; it++) {
            int cl = lane + 32 * it;
            float v = p[cl];
            float rv = v - sT[cl];
            if (rv > rbm) { rbm = rv; rbi = (unsigned)(bcol + cl); }
            float cv = v - uu;
            if (cv > cbm[it]) { cbm[it] = cv; cbi[it] = (unsigned)row; }
        }
#pragma unroll
        for (int off = 16; off; off >>= 1) {
            float om = __shfl_down_sync(0xffffffffu, rbm, off);
            unsigned oi = __shfl_down_sync(0xffffffffu, rbi, off);
            if (om > rbm) { rbm = om; rbi = oi; }
        }
        if (lane == 0) atomicMax(&g_rowBest[row], packfi(rbm, rbi));
    }
#pragma unroll
    for (int it = 0; it < 4; it++) {
        sCm[wid][lane + 32 * it] = cbm[it];
        sCi[wid][lane + 32 * it] = cbi[it];
    }
    __syncthreads();
    if (tid < 128) {
        float m = sCm[0][tid];
        unsigned idx = sCi[0][tid];
#pragma unroll
        for (int w = 1; w < 8; w++)
            if (sCm[w][tid] > m) { m = sCm[w][tid]; idx = sCi[w][tid]; }
        atomicMax(&g_colBest[bcol + tid], packfi(m, idx));
    }
}

// ---------------------------------------------------------------- sparse scatter of surviving matches
__global__ void k_scatter(float* __restrict__ out) {
    int i = blockIdx.x * blockDim.x + threadIdx.x;
    if (i >= L) return;
    unsigned long long rb = g_rowBest[i];
    unsigned j = (unsigned)rb;
    float val = unpackf(rb);              // max_j (sim_ij - t_j)
    float conf = __expf(val - g_u[i]);    // row/col-normalized dual-softmax confidence
    if (!(conf > 0.2f)) return;
    int r0 = i / HW, c0 = i % HW, r1 = (int)j / HW, c1 = (int)j % HW;
    if (r0 < MARG || r0 >= HW - MARG || c0 < MARG || c0 >= HW - MARG ||
        r1 < MARG || r1 >= HW - MARG || c1 < MARG || c1 >= HW - MARG) return;
    if ((unsigned)g_colBest[j] != (unsigned)i) return;   // mutual top-1
    out[(size_t)i * L + j] = conf;
}

extern "C" void kernel_launch(void* const* d_in, const int* in_sizes, int n_in,
                              void* d_out, int out_size) {
    const float* x0 = (const float*)d_in[0];
    const float* x1 = (const float*)d_in[1];
    float* out = (float*)d_out;

    dim3 tgrid(NT, NT);
    k_convert<<<(L * CDIM + 255) / 256, 256>>>(x0, x1);
    k_init<<<(L + 255) / 256, 256>>>();
    k_gemm<<<tgrid, 256>>>();
    k_stats<<<tgrid, 256>>>();
    k_combine<<<(L + 255) / 256, 256>>>();
    k_argmax<<<tgrid, 256>>>();
    k_zero<<<2048, 256>>>((float4*)out);
    k_scatter<<<(L + 255) / 256, 256>>>(out);
}

// round 3
// speedup vs baseline: 1.9041x; 1.9041x over previous
#include <cuda_runtime.h>
#include <cuda_bf16.h>
#include <math.h>
#include <stdint.h>

#define L 6400
#define CDIM 256
#define HW 80
#define MARG 2
#define TILE 128
#define NT (L / TILE)   // 50

__device__ __nv_bfloat16 g_x0[L * CDIM];
__device__ __nv_bfloat16 g_x1[L * CDIM];
__device__ float g_sim[(size_t)L * L];
__device__ float g_rowS[L];
__device__ float g_colS[L];
__device__ float g_u[L];
__device__ float g_t[L];
__device__ unsigned long long g_rowBest[L];
__device__ unsigned long long g_colBest[L];

__device__ __forceinline__ unsigned long long packfi(float v, unsigned idx) {
    unsigned b = __float_as_uint(v);
    b = (b & 0x80000000u) ? ~b : (b | 0x80000000u);
    return ((unsigned long long)b << 32) | (unsigned long long)idx;
}

__device__ __forceinline__ float unpackf(unsigned long long p) {
    unsigned b = (unsigned)(p >> 32);
    b = (b & 0x80000000u) ? (b ^ 0x80000000u) : ~b;
    return __uint_as_float(b);
}

// ---------------------------------------------------------------- convert
__global__ void k_convert(const float* __restrict__ x0, const float* __restrict__ x1) {
    int i = blockIdx.x * blockDim.x + threadIdx.x;
    if (i < L * CDIM) {
        g_x0[i] = __float2bfloat16(x0[i]);
        g_x1[i] = __float2bfloat16(x1[i]);
    }
}

__global__ void k_init() {
    int i = blockIdx.x * blockDim.x + threadIdx.x;
    if (i < L) {
        g_rowBest[i] = 0ull; g_colBest[i] = 0ull;
        g_rowS[i] = 0.f;     g_colS[i] = 0.f;
    }
}

__global__ void k_zero(float4* __restrict__ out) {
    size_t n4 = (size_t)L * L / 4;
    for (size_t i = (size_t)blockIdx.x * blockDim.x + threadIdx.x; i < n4;
         i += (size_t)gridDim.x * blockDim.x)
        out[i] = make_float4(0.f, 0.f, 0.f, 0.f);
}

// ---------------------------------------------------------------- GEMM: sim = x0 * x1^T / 25.6
// 128x128 tile per block, 8 warps in 4x2; each warp: 32 rows x 64 cols via m16n8k16 bf16 mma.
// Epilogue: store scaled sim AND accumulate exp-sums per row/col (no max shift needed:
// |sim| <= ~3.5 so exp is safe in fp32).
__global__ __launch_bounds__(256) void k_gemm() {
    __shared__ __nv_bfloat16 As[TILE][72];
    __shared__ __nv_bfloat16 Bs[TILE][72];
    const int tid = threadIdx.x;
    const int lane = tid & 31, wid = tid >> 5;
    const int wr = wid >> 1, wc = wid & 1;
    const int g = lane >> 2, tg = lane & 3;
    const int brow = blockIdx.y * TILE, bcol = blockIdx.x * TILE;

    float c[2][8][4];
#pragma unroll
    for (int mf = 0; mf < 2; mf++)
#pragma unroll
        for (int nf = 0; nf < 8; nf++)
#pragma unroll
            for (int q = 0; q < 4; q++) c[mf][nf][q] = 0.f;

    for (int kc = 0; kc < CDIM; kc += 64) {
        for (int x = tid; x < TILE * 8; x += 256) {
            int r = x >> 3, s = x & 7;
            uint4 qa = *(const uint4*)&g_x0[(size_t)(brow + r) * CDIM + kc + s * 8];
            uint4 qb = *(const uint4*)&g_x1[(size_t)(bcol + r) * CDIM + kc + s * 8];
            *(uint2*)&As[r][s * 8]     = make_uint2(qa.x, qa.y);
            *(uint2*)&As[r][s * 8 + 4] = make_uint2(qa.z, qa.w);
            *(uint2*)&Bs[r][s * 8]     = make_uint2(qb.x, qb.y);
            *(uint2*)&Bs[r][s * 8 + 4] = make_uint2(qb.z, qb.w);
        }
        __syncthreads();
#pragma unroll
        for (int kk = 0; kk < 64; kk += 16) {
            unsigned a[2][4], b[8][2];
#pragma unroll
            for (int mf = 0; mf < 2; mf++) {
                int r = wr * 32 + mf * 16;
                a[mf][0] = *(const unsigned*)&As[r + g][kk + 2 * tg];
                a[mf][1] = *(const unsigned*)&As[r + g + 8][kk + 2 * tg];
                a[mf][2] = *(const unsigned*)&As[r + g][kk + 2 * tg + 8];
                a[mf][3] = *(const unsigned*)&As[r + g + 8][kk + 2 * tg + 8];
            }
#pragma unroll
            for (int nf = 0; nf < 8; nf++) {
                int cc = wc * 64 + nf * 8;
                b[nf][0] = *(const unsigned*)&Bs[cc + g][kk + 2 * tg];
                b[nf][1] = *(const unsigned*)&Bs[cc + g][kk + 2 * tg + 8];
            }
#pragma unroll
            for (int mf = 0; mf < 2; mf++)
#pragma unroll
                for (int nf = 0; nf < 8; nf++) {
                    asm volatile(
                        "mma.sync.aligned.m16n8k16.row.col.f32.bf16.bf16.f32 "
                        "{%0,%1,%2,%3},{%4,%5,%6,%7},{%8,%9},{%0,%1,%2,%3};\n"
                        : "+f"(c[mf][nf][0]), "+f"(c[mf][nf][1]),
                          "+f"(c[mf][nf][2]), "+f"(c[mf][nf][3])
                        : "r"(a[mf][0]), "r"(a[mf][1]), "r"(a[mf][2]), "r"(a[mf][3]),
                          "r"(b[nf][0]), "r"(b[nf][1]));
                }
        }
        __syncthreads();
    }

    // -------- epilogue: scale, store, and accumulate exp-sums --------
    const float SCALE = 1.0f / 25.6f;
    float rsum_lo[2] = {0.f, 0.f}, rsum_hi[2] = {0.f, 0.f};
    float csum[8][2];
#pragma unroll
    for (int nf = 0; nf < 8; nf++) { csum[nf][0] = 0.f; csum[nf][1] = 0.f; }

#pragma unroll
    for (int mf = 0; mf < 2; mf++) {
        int r0 = brow + wr * 32 + mf * 16 + g;
#pragma unroll
        for (int nf = 0; nf < 8; nf++) {
            int cb = bcol + wc * 64 + nf * 8 + 2 * tg;
            float s0 = c[mf][nf][0] * SCALE;
            float s1 = c[mf][nf][1] * SCALE;
            float s2 = c[mf][nf][2] * SCALE;
            float s3 = c[mf][nf][3] * SCALE;
            *(float2*)&g_sim[(size_t)r0 * L + cb]       = make_float2(s0, s1);
            *(float2*)&g_sim[(size_t)(r0 + 8) * L + cb] = make_float2(s2, s3);
            float e0 = __expf(s0), e1 = __expf(s1), e2 = __expf(s2), e3 = __expf(s3);
            rsum_lo[mf] += e0 + e1;
            rsum_hi[mf] += e2 + e3;
            csum[nf][0] += e0 + e2;
            csum[nf][1] += e1 + e3;
        }
    }
    // row sums: reduce across tg (lanes {4g..4g+3})
#pragma unroll
    for (int mf = 0; mf < 2; mf++) {
        float lo = rsum_lo[mf], hi = rsum_hi[mf];
        lo += __shfl_xor_sync(0xffffffffu, lo, 1);
        lo += __shfl_xor_sync(0xffffffffu, lo, 2);
        hi += __shfl_xor_sync(0xffffffffu, hi, 1);
        hi += __shfl_xor_sync(0xffffffffu, hi, 2);
        if (tg == 0) {
            int r0 = brow + wr * 32 + mf * 16 + g;
            atomicAdd(&g_rowS[r0], lo);
            atomicAdd(&g_rowS[r0 + 8], hi);
        }
    }
    // col sums: reduce across g (lanes {tg, tg+4, ..., tg+28})
#pragma unroll
    for (int nf = 0; nf < 8; nf++) {
#pragma unroll
        for (int k = 0; k < 2; k++) {
            float s = csum[nf][k];
            s += __shfl_xor_sync(0xffffffffu, s, 4);
            s += __shfl_xor_sync(0xffffffffu, s, 8);
            s += __shfl_xor_sync(0xffffffffu, s, 16);
            if (g == 0)
                atomicAdd(&g_colS[bcol + wc * 64 + nf * 8 + 2 * tg + k], s);
        }
    }
}

// ---------------------------------------------------------------- combine: log of sums
__global__ void k_combine() {
    int i = blockIdx.x * blockDim.x + threadIdx.x;
    if (i >= L) return;
    g_u[i] = logf(g_rowS[i]);
    g_t[i] = logf(g_colS[i]);
}

// ---------------------------------------------------------------- argmax of log-conf along rows and cols
// Vectorized: each lane owns 4 contiguous cols of the 128-col tile (float4 loads),
// 2-row unroll for MLP. 8 warps x 16 rows each.
__global__ __launch_bounds__(256) void k_argmax() {
    __shared__ float sT[128];
    __shared__ float sU[128];
    __shared__ float sCm[8][128];
    __shared__ unsigned sCi[8][128];
    const int tid = threadIdx.x, lane = tid & 31, wid = tid >> 5;
    const int brow = blockIdx.y * TILE, bcol = blockIdx.x * TILE;
    if (tid < 128) { sT[tid] = g_t[bcol + tid]; sU[tid] = g_u[brow + tid]; }
    __syncthreads();

    float t0 = sT[lane * 4], t1 = sT[lane * 4 + 1], t2 = sT[lane * 4 + 2], t3 = sT[lane * 4 + 3];

    float cbm[4];
    unsigned cbi[4];
#pragma unroll
    for (int k = 0; k < 4; k++) { cbm[k] = -INFINITY; cbi[k] = 0u; }

#pragma unroll 2
    for (int r2 = 0; r2 < 16; r2 += 2) {
        int rowA = brow + wid * 16 + r2;
        int rowB = rowA + 1;
        float4 va = *(const float4*)&g_sim[(size_t)rowA * L + bcol + lane * 4];
        float4 vb = *(const float4*)&g_sim[(size_t)rowB * L + bcol + lane * 4];
        float uA = sU[wid * 16 + r2], uB = sU[wid * 16 + r2 + 1];

        // ---- row A ----
        float rbm; unsigned rbi;
        {
            float r0 = va.x - t0, r1 = va.y - t1, r2v = va.z - t2, r3 = va.w - t3;
            rbm = r0; rbi = (unsigned)(bcol + lane * 4);
            if (r1 > rbm) { rbm = r1; rbi = (unsigned)(bcol + lane * 4 + 1); }
            if (r2v > rbm) { rbm = r2v; rbi = (unsigned)(bcol + lane * 4 + 2); }
            if (r3 > rbm) { rbm = r3; rbi = (unsigned)(bcol + lane * 4 + 3); }
#pragma unroll
            for (int off = 16; off; off >>= 1) {
                float om = __shfl_down_sync(0xffffffffu, rbm, off);
                unsigned oi = __shfl_down_sync(0xffffffffu, rbi, off);
                if (om > rbm) { rbm = om; rbi = oi; }
            }
            if (lane == 0) atomicMax(&g_rowBest[rowA], packfi(rbm, rbi));
        }
        // col updates from row A
        {
            float c0 = va.x - uA, c1 = va.y - uA, c2 = va.z - uA, c3 = va.w - uA;
            if (c0 > cbm[0]) { cbm[0] = c0; cbi[0] = (unsigned)rowA; }
            if (c1 > cbm[1]) { cbm[1] = c1; cbi[1] = (unsigned)rowA; }
            if (c2 > cbm[2]) { cbm[2] = c2; cbi[2] = (unsigned)rowA; }
            if (c3 > cbm[3]) { cbm[3] = c3; cbi[3] = (unsigned)rowA; }
        }
        // ---- row B ----
        {
            float r0 = vb.x - t0, r1 = vb.y - t1, r2v = vb.z - t2, r3 = vb.w - t3;
            rbm = r0; rbi = (unsigned)(bcol + lane * 4);
            if (r1 > rbm) { rbm = r1; rbi = (unsigned)(bcol + lane * 4 + 1); }
            if (r2v > rbm) { rbm = r2v; rbi = (unsigned)(bcol + lane * 4 + 2); }
            if (r3 > rbm) { rbm = r3; rbi = (unsigned)(bcol + lane * 4 + 3); }
#pragma unroll
            for (int off = 16; off; off >>= 1) {
                float om = __shfl_down_sync(0xffffffffu, rbm, off);
                unsigned oi = __shfl_down_sync(0xffffffffu, rbi, off);
                if (om > rbm) { rbm = om; rbi = oi; }
            }
            if (lane == 0) atomicMax(&g_rowBest[rowB], packfi(rbm, rbi));
        }
        {
            float c0 = vb.x - uB, c1 = vb.y - uB, c2 = vb.z - uB, c3 = vb.w - uB;
            if (c0 > cbm[0]) { cbm[0] = c0; cbi[0] = (unsigned)rowB; }
            if (c1 > cbm[1]) { cbm[1] = c1; cbi[1] = (unsigned)rowB; }
            if (c2 > cbm[2]) { cbm[2] = c2; cbi[2] = (unsigned)rowB; }
            if (c3 > cbm[3]) { cbm[3] = c3; cbi[3] = (unsigned)rowB; }
        }
    }
#pragma unroll
    for (int k = 0; k < 4; k++) {
        sCm[wid][lane * 4 + k] = cbm[k];
        sCi[wid][lane * 4 + k] = cbi[k];
    }
    __syncthreads();
    if (tid < 128) {
        float m = sCm[0][tid];
        unsigned idx = sCi[0][tid];
#pragma unroll
        for (int w = 1; w < 8; w++)
            if (sCm[w][tid] > m) { m = sCm[w][tid]; idx = sCi[w][tid]; }
        atomicMax(&g_colBest[bcol + tid], packfi(m, idx));
    }
}

// ---------------------------------------------------------------- sparse scatter of surviving matches
__global__ void k_scatter(float* __restrict__ out) {
    int i = blockIdx.x * blockDim.x + threadIdx.x;
    if (i >= L) return;
    unsigned long long rb = g_rowBest[i];
    unsigned j = (unsigned)rb;
    float val = unpackf(rb);              // max_j (sim_ij - t_j)
    float conf = __expf(val - g_u[i]);    // dual-softmax confidence at row-best
    if (!(conf > 0.2f)) return;
    int r0 = i / HW, c0 = i % HW, r1 = (int)j / HW, c1 = (int)j % HW;
    if (r0 < MARG || r0 >= HW - MARG || c0 < MARG || c0 >= HW - MARG ||
        r1 < MARG || r1 >= HW - MARG || c1 < MARG || c1 >= HW - MARG) return;
    if ((unsigned)g_colBest[j] != (unsigned)i) return;   // mutual top-1
    out[(size_t)i * L + j] = conf;
}

extern "C" void kernel_launch(void* const* d_in, const int* in_sizes, int n_in,
                              void* d_out, int out_size) {
    const float* x0 = (const float*)d_in[0];
    const float* x1 = (const float*)d_in[1];
    float* out = (float*)d_out;

    dim3 tgrid(NT, NT);
    k_convert<<<(L * CDIM + 255) / 256, 256>>>(x0, x1);
    k_init<<<(L + 255) / 256, 256>>>();
    k_gemm<<<tgrid, 256>>>();
    k_combine<<<(L + 255) / 256, 256>>>();
    k_argmax<<<tgrid, 256>>>();
    k_zero<<<2048, 256>>>((float4*)out);
    k_scatter<<<(L + 255) / 256, 256>>>(out);
}